// round 13
// baseline (speedup 1.0000x reference)
#include <cuda_runtime.h>
#include <cuda_fp16.h>
#include <cstdint>

// out[h,n,t] = q·k_quant^T + (qG/R)·sign((k_orig-k_quant)G)^T
// Single-pass fp16 augmented GEMM, K = 192:
//   Q'[h,n,:] = [ fp16(q) , fp16((q@G)/R) ]
//   K'[h,t,:] = [ fp16(k_quant) , fp16(sign((k_orig-k_quant)@G)) ] (sign in fp32)
// Persistent GEMM, 2 CTAs/SM (256 thr, tile 128x128), rolling 3-slot cp.async
// ring, register double-buffered ldmatrix fragments.

#define HH 32
#define NN 2048
#define TT 2048
#define DD 128
#define RR 64
#define KD 192
#define NTILES 8192   // 32 heads * 16 m-tiles * 16 n-tiles (128x128)

__device__ __align__(16) __half g_Qa[(size_t)HH * NN * KD];
__device__ __align__(16) __half g_Ka[(size_t)HH * TT * KD];

static __device__ __forceinline__ uint32_t smem_u32(const void* p) {
    uint32_t a;
    asm("{ .reg .u64 t; cvta.to.shared.u64 t, %1; cvt.u32.u64 %0, t; }"
        : "=r"(a) : "l"(p));
    return a;
}

static __device__ __forceinline__ void cp16(uint32_t d, const void* s) {
    asm volatile("cp.async.cg.shared.global [%0], [%1], 16;" :: "r"(d), "l"(s) : "memory");
}

static __device__ __forceinline__ void ldsm4(uint32_t& r0, uint32_t& r1, uint32_t& r2,
                                             uint32_t& r3, uint32_t a) {
    asm volatile("ldmatrix.sync.aligned.m8n8.x4.shared.b16 {%0,%1,%2,%3}, [%4];"
                 : "=r"(r0), "=r"(r1), "=r"(r2), "=r"(r3) : "r"(a));
}

static __device__ __forceinline__ void mma16816(float* c, const uint32_t* a, const uint32_t* b) {
    asm volatile(
        "mma.sync.aligned.m16n8k16.row.col.f32.f16.f16.f32 "
        "{%0,%1,%2,%3}, {%4,%5,%6,%7}, {%8,%9}, {%0,%1,%2,%3};"
        : "+f"(c[0]), "+f"(c[1]), "+f"(c[2]), "+f"(c[3])
        : "r"(a[0]), "r"(a[1]), "r"(a[2]), "r"(a[3]), "r"(b[0]), "r"(b[1]));
}

static __device__ __forceinline__ uint32_t pack_h2(__half a, __half b) {
    __half2 t = __halves2half2(a, b);
    return *reinterpret_cast<uint32_t*>(&t);
}

// ---------------------------------------------------------------------------
// Fused prep: blocks [0,2048) do Q rows, [2048,4096) do K rows.
// ---------------------------------------------------------------------------
__global__ __launch_bounds__(256) void prep_all(const float* __restrict__ q,
                                                const float* __restrict__ k_orig,
                                                const float* __restrict__ k_quant,
                                                const float* __restrict__ G) {
    __shared__ float Gs[DD * RR];
    __shared__ float Es[32][DD];
    const int tid = threadIdx.x;
    const bool isQ = blockIdx.x < 2048;

    const float4* G4 = (const float4*)G;
    float4* Gs4 = (float4*)Gs;
    #pragma unroll
    for (int i = tid; i < DD * RR / 4; i += 256) Gs4[i] = G4[i];

    const size_t row0 = (size_t)(isQ ? blockIdx.x : (blockIdx.x - 2048)) * 32;
    __half* dst = isQ ? g_Qa : g_Ka;

    if (isQ) {
        #pragma unroll
        for (int i = tid; i < 32 * 32; i += 256) {
            int r = i >> 5, c = i & 31;
            float4 v = *(const float4*)(q + (row0 + r) * DD + c * 4);
            *(float4*)(&Es[r][c * 4]) = v;
            size_t o = (row0 + r) * KD + c * 4;
            *(uint2*)(&dst[o]) = make_uint2(
                pack_h2(__float2half_rn(v.x), __float2half_rn(v.y)),
                pack_h2(__float2half_rn(v.z), __float2half_rn(v.w)));
        }
    } else {
        #pragma unroll
        for (int i = tid; i < 32 * 32; i += 256) {
            int r = i >> 5, c = i & 31;
            float4 vq = *(const float4*)(k_quant + (row0 + r) * DD + c * 4);
            float4 vo = *(const float4*)(k_orig + (row0 + r) * DD + c * 4);
            float4 e4;
            e4.x = vo.x - vq.x; e4.y = vo.y - vq.y;
            e4.z = vo.z - vq.z; e4.w = vo.w - vq.w;
            *(float4*)(&Es[r][c * 4]) = e4;
            size_t o = (row0 + r) * KD + c * 4;
            *(uint2*)(&dst[o]) = make_uint2(
                pack_h2(__float2half_rn(vq.x), __float2half_rn(vq.y)),
                pack_h2(__float2half_rn(vq.z), __float2half_rn(vq.w)));
        }
    }
    __syncthreads();

    const int w = tid >> 5, lane = tid & 31;
    const int r0 = w * 4;
    float a0[4] = {0.f, 0.f, 0.f, 0.f}, a1[4] = {0.f, 0.f, 0.f, 0.f};
    #pragma unroll 4
    for (int d = 0; d < DD; ++d) {
        float gA = Gs[d * RR + lane];
        float gB = Gs[d * RR + 32 + lane];
        #pragma unroll
        for (int j = 0; j < 4; ++j) {
            float e = Es[r0 + j][d];
            a0[j] += e * gA;
            a1[j] += e * gB;
        }
    }
    if (isQ) {
        const float sc = 1.0f / (float)RR;
        #pragma unroll
        for (int j = 0; j < 4; ++j) {
            size_t o = (row0 + r0 + j) * KD + DD;
            dst[o + lane]      = __float2half_rn(a0[j] * sc);
            dst[o + 32 + lane] = __float2half_rn(a1[j] * sc);
        }
    } else {
        #pragma unroll
        for (int j = 0; j < 4; ++j) {
            float s0 = (a0[j] > 0.f) ? 1.f : ((a0[j] < 0.f) ? -1.f : 0.f);
            float s1 = (a1[j] > 0.f) ? 1.f : ((a1[j] < 0.f) ? -1.f : 0.f);
            size_t o = (row0 + r0 + j) * KD + DD;
            dst[o + lane]      = __float2half_rn(s0);
            dst[o + 32 + lane] = __float2half_rn(s1);
        }
    }
}

// ---------------------------------------------------------------------------
// Persistent HMMA GEMM, 2 CTAs/SM. CTA tile 128(M) x 128(N), 256 threads
// (8 warps, warp tile 64x32). Chunk stream: chunk c -> (tile c/3, stage c%3).
// Register double-buffered fragments. Rows padded to 144B (conflict-free
// ldmatrix). smem/CTA = 3 * 36864 = 110592 -> two CTAs fit in 228KB.
// ---------------------------------------------------------------------------
#define ROWB 144
#define A_BYTES (128 * ROWB)              // 18432
#define STAGE (2 * A_BYTES)               // 36864 (A + B)
#define SMEM_TOTAL (STAGE * 3)            // 110592
#define B_OFF A_BYTES

__global__ __launch_bounds__(256, 2) void gemm_persist(float* __restrict__ C) {
    extern __shared__ char sm[];
    const uint32_t smb = smem_u32(sm);
    const int tid = threadIdx.x, lane = tid & 31, wid = tid >> 5;
    const int wm = wid & 1;        // 0..1 -> 64-row m slot
    const int wn = wid >> 1;       // 0..3 -> 32-col n slot
    const int bid = blockIdx.x, grid = gridDim.x;

    const int myTiles = (bid < NTILES) ? ((NTILES - 1 - bid) / grid + 1) : 0;
    const int myChunks = myTiles * 3;
    if (myChunks == 0) return;

    auto issueChunk = [&](int c2) {
        const int t = c2 / 3, s = c2 - t * 3;
        const int tileIdx = bid + t * grid;
        const int h = tileIdx >> 8, rem = tileIdx & 255;
        const size_t arow0 = (size_t)h * NN + (size_t)(rem >> 4) * 128;
        const size_t brow0 = (size_t)h * TT + (size_t)(rem & 15) * 128;
        const uint32_t sA = smb + s * STAGE;
        const uint32_t sB = sA + B_OFF;
        const int c0 = s * 64;
        #pragma unroll
        for (int i = 0; i < 4; ++i) {         // A: 1024 16B chunks / 256 thr
            int u = tid + (i << 8);
            int r = u >> 3, cc = u & 7;
            cp16(sA + r * ROWB + cc * 16,
                 (const char*)(g_Qa + (arow0 + r) * KD + c0) + cc * 16);
        }
        #pragma unroll
        for (int i = 0; i < 4; ++i) {         // B: 1024 16B chunks
            int u = tid + (i << 8);
            int r = u >> 3, cc = u & 7;
            cp16(sB + r * ROWB + cc * 16,
                 (const char*)(g_Ka + (brow0 + r) * KD + c0) + cc * 16);
        }
        asm volatile("cp.async.commit_group;" ::: "memory");
    };

    float acc[4][4][4];
    #pragma unroll
    for (int i = 0; i < 4; ++i)
        #pragma unroll
        for (int j = 0; j < 4; ++j)
            #pragma unroll
            for (int v = 0; v < 4; ++v) acc[i][j][v] = 0.f;

    issueChunk(0);
    if (myChunks > 1) issueChunk(1);

    const uint32_t aB = smb + (uint32_t)(wm * 64 + (lane & 15)) * ROWB + (lane >> 4) * 16;
    const uint32_t bB = smb + B_OFF + (uint32_t)(wn * 32 + (lane & 15)) * ROWB + (lane >> 4) * 16;

    uint32_t afr[2][4][4];    // double-buffered A fragments
    uint32_t bfr[2][4][2];    // double-buffered B fragments

    auto ldFrag = [&](int buf, uint32_t so, int kc) {
        #pragma unroll
        for (int mt = 0; mt < 4; ++mt)
            ldsm4(afr[buf][mt][0], afr[buf][mt][1], afr[buf][mt][2], afr[buf][mt][3],
                  aB + so + kc * 32 + mt * (16 * ROWB));
        #pragma unroll
        for (int nb = 0; nb < 2; ++nb) {
            uint32_t r0, r1, r2, r3;
            ldsm4(r0, r1, r2, r3, bB + so + kc * 32 + nb * (16 * ROWB));
            bfr[buf][2 * nb][0] = r0;     bfr[buf][2 * nb][1] = r2;
            bfr[buf][2 * nb + 1][0] = r1; bfr[buf][2 * nb + 1][1] = r3;
        }
    };

    #pragma unroll 1
    for (int c = 0; c < myChunks; ++c) {
        const int t = c / 3, s = c - t * 3;

        if (c + 1 < myChunks) asm volatile("cp.async.wait_group 1;" ::: "memory");
        else                  asm volatile("cp.async.wait_group 0;" ::: "memory");
        __syncthreads();                     // data of chunk c visible; slot of c-1 free
        if (c + 2 < myChunks) issueChunk(c + 2);

        const uint32_t so = s * STAGE;
        ldFrag(0, so, 0);
        #pragma unroll
        for (int kc = 0; kc < 4; ++kc) {
            const int cur = kc & 1;
            if (kc < 3) ldFrag(cur ^ 1, so, kc + 1);   // prefetch before consuming cur
            #pragma unroll
            for (int mt = 0; mt < 4; ++mt)
                #pragma unroll
                for (int nt = 0; nt < 4; ++nt)
                    mma16816(acc[mt][nt], afr[cur][mt], bfr[cur][nt]);
        }

        if (s == 2) {
            // epilogue for this tile; overlaps in-flight loads of next tile
            const int tileIdx = bid + t * grid;
            const int h = tileIdx >> 8, rem = tileIdx & 255;
            float* Cb = C + ((size_t)h * NN + (size_t)(rem >> 4) * 128 + wm * 64) * TT
                          + (size_t)(rem & 15) * 128 + wn * 32;
            const int r = lane >> 2, cc = (lane & 3) * 2;
            #pragma unroll
            for (int mt = 0; mt < 4; ++mt) {
                #pragma unroll
                for (int nt = 0; nt < 4; ++nt) {
                    float2 v0 = make_float2(acc[mt][nt][0], acc[mt][nt][1]);
                    float2 v1 = make_float2(acc[mt][nt][2], acc[mt][nt][3]);
                    __stcs((float2*)(Cb + (size_t)(mt * 16 + r) * TT + nt * 8 + cc), v0);
                    __stcs((float2*)(Cb + (size_t)(mt * 16 + r + 8) * TT + nt * 8 + cc), v1);
                    acc[mt][nt][0] = 0.f; acc[mt][nt][1] = 0.f;
                    acc[mt][nt][2] = 0.f; acc[mt][nt][3] = 0.f;
                }
            }
        }
    }
}

// ---------------------------------------------------------------------------
extern "C" void kernel_launch(void* const* d_in, const int* in_sizes, int n_in,
                              void* d_out, int out_size) {
    const float* q       = (const float*)d_in[0];
    const float* k_orig  = (const float*)d_in[1];
    const float* k_quant = (const float*)d_in[2];
    const float* G       = (const float*)d_in[3];
    float* out = (float*)d_out;

    int dev = 0, nsm = 148;
    cudaGetDevice(&dev);
    cudaDeviceGetAttribute(&nsm, cudaDevAttrMultiProcessorCount, dev);

    cudaFuncSetAttribute(gemm_persist, cudaFuncAttributeMaxDynamicSharedMemorySize, SMEM_TOTAL);

    prep_all<<<4096, 256>>>(q, k_orig, k_quant, G);
    gemm_persist<<<2 * nsm, 256, SMEM_TOTAL>>>(out);
}

// round 14
// speedup vs baseline: 1.1566x; 1.1566x over previous
#include <cuda_runtime.h>
#include <cuda_fp16.h>
#include <cstdint>

// out[h,n,t] = q·k_quant^T + (qG/R)·sign((k_orig-k_quant)G)^T
// Single-pass fp16 augmented GEMM, K = 192.
// Prep writes operands as PADDED SMEM TILE-IMAGES (128 rows x 144B per
// 64-col stage); GEMM fetches each stage with ONE cp.async.bulk per operand
// (mbarrier complete_tx), eliminating the LDGSTS issue bottleneck
// (was 2048 x 8cyc/SMSP per chunk).

#define HH 32
#define NN 2048
#define TT 2048
#define DD 128
#define RR 64
#define KD 192
#define NTILES 8192   // 32 heads * 16 m-tiles * 16 n-tiles (128x128)

#define ROWB 144
#define IMG  18432            // one stage image: 128 rows * 144B
// images: [h][tile16][stage3] ; 32*16*3*18432 = 28.3 MB each
__device__ __align__(128) char g_Qi[(size_t)HH * 16 * 3 * IMG];
__device__ __align__(128) char g_Ki[(size_t)HH * 16 * 3 * IMG];

static __device__ __forceinline__ uint32_t smem_u32(const void* p) {
    uint32_t a;
    asm("{ .reg .u64 t; cvta.to.shared.u64 t, %1; cvt.u32.u64 %0, t; }"
        : "=r"(a) : "l"(p));
    return a;
}

static __device__ __forceinline__ void ldsm4(uint32_t& r0, uint32_t& r1, uint32_t& r2,
                                             uint32_t& r3, uint32_t a) {
    asm volatile("ldmatrix.sync.aligned.m8n8.x4.shared.b16 {%0,%1,%2,%3}, [%4];"
                 : "=r"(r0), "=r"(r1), "=r"(r2), "=r"(r3) : "r"(a));
}

static __device__ __forceinline__ void mma16816(float* c, const uint32_t* a, const uint32_t* b) {
    asm volatile(
        "mma.sync.aligned.m16n8k16.row.col.f32.f16.f16.f32 "
        "{%0,%1,%2,%3}, {%4,%5,%6,%7}, {%8,%9}, {%0,%1,%2,%3};"
        : "+f"(c[0]), "+f"(c[1]), "+f"(c[2]), "+f"(c[3])
        : "r"(a[0]), "r"(a[1]), "r"(a[2]), "r"(a[3]), "r"(b[0]), "r"(b[1]));
}

static __device__ __forceinline__ uint32_t pack_h2(__half a, __half b) {
    __half2 t = __halves2half2(a, b);
    return *reinterpret_cast<uint32_t*>(&t);
}

static __device__ __forceinline__ void mbar_init(uint32_t addr, uint32_t cnt) {
    asm volatile("mbarrier.init.shared.b64 [%0], %1;" :: "r"(addr), "r"(cnt) : "memory");
}

static __device__ __forceinline__ void mbar_expect_tx(uint32_t addr, uint32_t bytes) {
    asm volatile("mbarrier.arrive.expect_tx.shared.b64 _, [%0], %1;"
                 :: "r"(addr), "r"(bytes) : "memory");
}

static __device__ __forceinline__ void mbar_wait(uint32_t addr, uint32_t parity) {
    asm volatile(
        "{\n\t"
        ".reg .pred P;\n\t"
        "WL_%=:\n\t"
        "mbarrier.try_wait.parity.acquire.cta.shared::cta.b64 P, [%0], %1, 0x989680;\n\t"
        "@P bra WD_%=;\n\t"
        "bra WL_%=;\n\t"
        "WD_%=:\n\t"
        "}"
        :: "r"(addr), "r"(parity) : "memory");
}

static __device__ __forceinline__ void bulkcp(uint32_t dst, const void* src,
                                              uint32_t bytes, uint32_t mbar) {
    asm volatile(
        "cp.async.bulk.shared::cluster.global.mbarrier::complete_tx::bytes [%0], [%1], %2, [%3];"
        :: "r"(dst), "l"(src), "r"(bytes), "r"(mbar) : "memory");
}

// ---------------------------------------------------------------------------
// Fused prep: blocks [0,2048) -> Q rows, [2048,4096) -> K rows.
// Emits the padded tile-image layout directly.
// Each block: 32 consecutive rows (within one head & one 128-row tile).
// ---------------------------------------------------------------------------
__global__ __launch_bounds__(256) void prep_all(const float* __restrict__ q,
                                                const float* __restrict__ k_orig,
                                                const float* __restrict__ k_quant,
                                                const float* __restrict__ G) {
    __shared__ float Gs[DD * RR];
    __shared__ float Es[32][DD];
    const int tid = threadIdx.x;
    const bool isQ = blockIdx.x < 2048;

    const float4* G4 = (const float4*)G;
    float4* Gs4 = (float4*)Gs;
    #pragma unroll
    for (int i = tid; i < DD * RR / 4; i += 256) Gs4[i] = G4[i];

    const int blk = isQ ? blockIdx.x : (blockIdx.x - 2048);
    const size_t row0 = (size_t)blk * 32;
    const int h = blk >> 6;                 // 64 blocks per head (2048/32)
    const int nl0 = (blk & 63) * 32;        // row offset within head
    const int tile = nl0 >> 7;              // 128-row tile index
    const int rbase = nl0 & 127;            // row base within tile
    char* img = (isQ ? g_Qi : g_Ki) + ((size_t)(h * 16 + tile) * 3) * IMG;

    if (isQ) {
        #pragma unroll
        for (int i = tid; i < 32 * 32; i += 256) {
            int r = i >> 5, c = i & 31;
            float4 v = *(const float4*)(q + (row0 + r) * DD + c * 4);
            *(float4*)(&Es[r][c * 4]) = v;
            int col0 = c * 4, s = col0 >> 6, cc = col0 & 63;
            char* d = img + (size_t)s * IMG + (size_t)(rbase + r) * ROWB + cc * 2;
            *(uint2*)d = make_uint2(
                pack_h2(__float2half_rn(v.x), __float2half_rn(v.y)),
                pack_h2(__float2half_rn(v.z), __float2half_rn(v.w)));
        }
    } else {
        #pragma unroll
        for (int i = tid; i < 32 * 32; i += 256) {
            int r = i >> 5, c = i & 31;
            float4 vq = *(const float4*)(k_quant + (row0 + r) * DD + c * 4);
            float4 vo = *(const float4*)(k_orig + (row0 + r) * DD + c * 4);
            float4 e4;
            e4.x = vo.x - vq.x; e4.y = vo.y - vq.y;
            e4.z = vo.z - vq.z; e4.w = vo.w - vq.w;
            *(float4*)(&Es[r][c * 4]) = e4;
            int col0 = c * 4, s = col0 >> 6, cc = col0 & 63;
            char* d = img + (size_t)s * IMG + (size_t)(rbase + r) * ROWB + cc * 2;
            *(uint2*)d = make_uint2(
                pack_h2(__float2half_rn(vq.x), __float2half_rn(vq.y)),
                pack_h2(__float2half_rn(vq.z), __float2half_rn(vq.w)));
        }
    }
    __syncthreads();

    const int w = tid >> 5, lane = tid & 31;
    const int r0 = w * 4;
    float a0[4] = {0.f, 0.f, 0.f, 0.f}, a1[4] = {0.f, 0.f, 0.f, 0.f};
    #pragma unroll 4
    for (int d = 0; d < DD; ++d) {
        float gA = Gs[d * RR + lane];
        float gB = Gs[d * RR + 32 + lane];
        #pragma unroll
        for (int j = 0; j < 4; ++j) {
            float e = Es[r0 + j][d];
            a0[j] += e * gA;
            a1[j] += e * gB;
        }
    }
    char* img2 = img + 2 * (size_t)IMG;     // stage 2 holds cols 128..191
    if (isQ) {
        const float sc = 1.0f / (float)RR;
        #pragma unroll
        for (int j = 0; j < 4; ++j) {
            char* d = img2 + (size_t)(rbase + r0 + j) * ROWB;
            *((__half*)d + lane)      = __float2half_rn(a0[j] * sc);
            *((__half*)d + 32 + lane) = __float2half_rn(a1[j] * sc);
        }
    } else {
        #pragma unroll
        for (int j = 0; j < 4; ++j) {
            float s0 = (a0[j] > 0.f) ? 1.f : ((a0[j] < 0.f) ? -1.f : 0.f);
            float s1 = (a1[j] > 0.f) ? 1.f : ((a1[j] < 0.f) ? -1.f : 0.f);
            char* d = img2 + (size_t)(rbase + r0 + j) * ROWB;
            *((__half*)d + lane)      = __float2half_rn(s0);
            *((__half*)d + 32 + lane) = __float2half_rn(s1);
        }
    }
}

// ---------------------------------------------------------------------------
// Persistent HMMA GEMM, 2 CTAs/SM. CTA tile 128x128, 256 threads (8 warps,
// warp 64x32). Chunk c -> (tile c/3, stage c%3), smem slot c%3, parity (c/3)&1.
// Stage fill: thread 0 issues expect_tx + 2 bulk copies; everyone waits on
// the slot's mbarrier. __syncthreads before issuing into slot of chunk c-1.
// ---------------------------------------------------------------------------
#define HDR 128
#define STAGE (2 * IMG)                    // A image + B image = 36864
#define SMEM_TOTAL (HDR + 3 * STAGE)       // 110720 -> 2 CTAs/SM fit
#define B_OFF IMG

__global__ __launch_bounds__(256, 2) void gemm_persist(float* __restrict__ C) {
    extern __shared__ char sm[];
    const uint32_t smb = smem_u32(sm);
    const int tid = threadIdx.x, lane = tid & 31, wid = tid >> 5;
    const int wm = wid & 1;        // 0..1 -> 64-row m slot
    const int wn = wid >> 1;       // 0..3 -> 32-col n slot
    const int bid = blockIdx.x, grid = gridDim.x;

    const int myTiles = (bid < NTILES) ? ((NTILES - 1 - bid) / grid + 1) : 0;
    const int myChunks = myTiles * 3;
    if (myChunks == 0) return;

    if (tid == 0) {
        mbar_init(smb + 0, 1);
        mbar_init(smb + 8, 1);
        mbar_init(smb + 16, 1);
    }
    __syncthreads();

    auto issueChunk = [&](int c2) {        // thread 0 only
        const int t = c2 / 3, s = c2 - t * 3;
        const int tileIdx = bid + t * grid;
        const int h = tileIdx >> 8, rem = tileIdx & 255;
        const char* srcA = g_Qi + ((size_t)(h * 16 + (rem >> 4)) * 3 + s) * IMG;
        const char* srcB = g_Ki + ((size_t)(h * 16 + (rem & 15)) * 3 + s) * IMG;
        const uint32_t mb = smb + s * 8;
        const uint32_t dst = smb + HDR + s * STAGE;
        mbar_expect_tx(mb, 2 * IMG);
        bulkcp(dst, srcA, IMG, mb);
        bulkcp(dst + B_OFF, srcB, IMG, mb);
    };

    float acc[4][4][4];
    #pragma unroll
    for (int i = 0; i < 4; ++i)
        #pragma unroll
        for (int j = 0; j < 4; ++j)
            #pragma unroll
            for (int v = 0; v < 4; ++v) acc[i][j][v] = 0.f;

    if (tid == 0) {
        issueChunk(0);
        if (myChunks > 1) issueChunk(1);
    }

    const uint32_t aB = smb + HDR + (uint32_t)(wm * 64 + (lane & 15)) * ROWB + (lane >> 4) * 16;
    const uint32_t bB = smb + HDR + B_OFF + (uint32_t)(wn * 32 + (lane & 15)) * ROWB + (lane >> 4) * 16;

    uint32_t afr[2][4][4];
    uint32_t bfr[2][4][2];

    auto ldFrag = [&](int buf, uint32_t so, int kc) {
        #pragma unroll
        for (int mt = 0; mt < 4; ++mt)
            ldsm4(afr[buf][mt][0], afr[buf][mt][1], afr[buf][mt][2], afr[buf][mt][3],
                  aB + so + kc * 32 + mt * (16 * ROWB));
        #pragma unroll
        for (int nb = 0; nb < 2; ++nb) {
            uint32_t r0, r1, r2, r3;
            ldsm4(r0, r1, r2, r3, bB + so + kc * 32 + nb * (16 * ROWB));
            bfr[buf][2 * nb][0] = r0;     bfr[buf][2 * nb][1] = r2;
            bfr[buf][2 * nb + 1][0] = r1; bfr[buf][2 * nb + 1][1] = r3;
        }
    };

    #pragma unroll 1
    for (int c = 0; c < myChunks; ++c) {
        const int t = c / 3, s = c - t * 3;

        mbar_wait(smb + s * 8, (t & 1));     // chunk c data ready (acquire)
        __syncthreads();                     // all warps done with chunk c-1's slot
        if (tid == 0 && c + 2 < myChunks) issueChunk(c + 2);

        const uint32_t so = s * STAGE;
        ldFrag(0, so, 0);
        #pragma unroll
        for (int kc = 0; kc < 4; ++kc) {
            const int cur = kc & 1;
            if (kc < 3) ldFrag(cur ^ 1, so, kc + 1);
            #pragma unroll
            for (int mt = 0; mt < 4; ++mt)
                #pragma unroll
                for (int nt = 0; nt < 4; ++nt)
                    mma16816(acc[mt][nt], afr[cur][mt], bfr[cur][nt]);
        }

        if (s == 2) {
            const int tileIdx = bid + t * grid;
            const int h = tileIdx >> 8, rem = tileIdx & 255;
            float* Cb = C + ((size_t)h * NN + (size_t)(rem >> 4) * 128 + wm * 64) * TT
                          + (size_t)(rem & 15) * 128 + wn * 32;
            const int r = lane >> 2, cc = (lane & 3) * 2;
            #pragma unroll
            for (int mt = 0; mt < 4; ++mt) {
                #pragma unroll
                for (int nt = 0; nt < 4; ++nt) {
                    float2 v0 = make_float2(acc[mt][nt][0], acc[mt][nt][1]);
                    float2 v1 = make_float2(acc[mt][nt][2], acc[mt][nt][3]);
                    __stcs((float2*)(Cb + (size_t)(mt * 16 + r) * TT + nt * 8 + cc), v0);
                    __stcs((float2*)(Cb + (size_t)(mt * 16 + r + 8) * TT + nt * 8 + cc), v1);
                    acc[mt][nt][0] = 0.f; acc[mt][nt][1] = 0.f;
                    acc[mt][nt][2] = 0.f; acc[mt][nt][3] = 0.f;
                }
            }
        }
    }
}

// ---------------------------------------------------------------------------
extern "C" void kernel_launch(void* const* d_in, const int* in_sizes, int n_in,
                              void* d_out, int out_size) {
    const float* q       = (const float*)d_in[0];
    const float* k_orig  = (const float*)d_in[1];
    const float* k_quant = (const float*)d_in[2];
    const float* G       = (const float*)d_in[3];
    float* out = (float*)d_out;

    int dev = 0, nsm = 148;
    cudaGetDevice(&dev);
    cudaDeviceGetAttribute(&nsm, cudaDevAttrMultiProcessorCount, dev);

    cudaFuncSetAttribute(gemm_persist, cudaFuncAttributeMaxDynamicSharedMemorySize, SMEM_TOTAL);

    prep_all<<<4096, 256>>>(q, k_orig, k_quant, G);
    gemm_persist<<<2 * nsm, 256, SMEM_TOTAL>>>(out);
}